// round 5
// baseline (speedup 1.0000x reference)
#include <cuda_runtime.h>
#include <cstdint>
#include <cstddef>

#define B_ 256
#define T_ 256
#define D_ 512
#define H_ 1024
#define C_ 10

#define NCTA 128
#define NTHR 128
#define TM 32
#define TN 64
#define TK 32

// h ping-pong buffers: h after step t lives in g_h[(t+1)&1].
// t=0 never reads h (h0 == 0 handled by skipping U-GEMM and beta term).
// Referenced ONLY from device code (host address-of a __device__ symbol
// resolves to the host shadow and trips the memory guard).
__device__ float g_h[2][B_ * H_];

// ---- packed f32x2 helpers (exact fp32 FMA, 2 lanes per instruction) ----
__device__ __forceinline__ void fma2(unsigned long long& d,
                                     unsigned long long a,
                                     unsigned long long b) {
    asm("fma.rn.f32x2 %0, %1, %2, %0;" : "+l"(d) : "l"(a), "l"(b));
}
__device__ __forceinline__ unsigned long long dup2(float v) {
    unsigned long long r;
    unsigned int u = __float_as_uint(v);
    asm("mov.b64 %0, {%1, %1};" : "=l"(r) : "r"(u));
    return r;
}
__device__ __forceinline__ float2 unpk2(unsigned long long p) {
    unsigned int lo, hi;
    asm("mov.b64 {%0, %1}, %2;" : "=r"(lo), "=r"(hi) : "l"(p));
    return make_float2(__uint_as_float(lo), __uint_as_float(hi));
}

// One fused recurrence step:
//   h_out = alpha * tanh(x_t @ Ww + h_in @ Uw + (Wb+Ub)) + beta * h_in
// Grid: 128 CTAs = 8 M-tiles(32) x 16 N-tiles(64). 128 threads, 4x4 per thread.
// Double-buffered smem, one __syncthreads per k-tile, packed f32x2 FMA.
__global__ void __launch_bounds__(NTHR, 1) step_kernel(
    const float* __restrict__ x,
    const float* __restrict__ Ww, const float* __restrict__ Wb,
    const float* __restrict__ Uw, const float* __restrict__ Ub,
    const float* __restrict__ alpha_p, const float* __restrict__ beta_p,
    int t)
{
    const float* __restrict__ h_in  = &g_h[t & 1][0];
    float* __restrict__       h_out = &g_h[(t + 1) & 1][0];

    __shared__ float As[2][TK][TM];      // A transposed: As[p][k][m]
    __shared__ float Bs[2][TK][TN];      // Bs[p][k][n]

    const int tid = threadIdx.x;
    const int bm = blockIdx.x & 7;       // 8 M-tiles of 32
    const int bn = blockIdx.x >> 3;      // 16 N-tiles of 64
    const int m0 = bm * TM;
    const int n0 = bn * TN;

    const int tx = tid & 15;             // 16 col-groups
    const int ty = tid >> 4;             // 8 row-groups
    const int mr = ty * 4;               // 4 rows per thread
    const int nc = tx * 4;               // 4 cols per thread

    const float alpha = alpha_p[0];
    const float beta  = beta_p[0];

    float bias[4];
    #pragma unroll
    for (int j = 0; j < 4; ++j)
        bias[j] = Wb[n0 + nc + j] + Ub[n0 + nc + j];

    // Loader lane mapping (128 threads)
    const int a_row = tid & 31;          // 0..31  (m within tile)
    const int a_k8  = (tid >> 5) * 8;    // 0,8,16,24 (k base, 8 k's per thread)
    const int b_k   = tid >> 4;          // 0..7   (k row; also +8,+16,+24)
    const int b_n4  = (tid & 15) * 4;    // 0..60

    // 8 packed accumulators: acc2[i][jp] = cols (nc+2jp, nc+2jp+1) of row mr+i
    unsigned long long acc2[4][2];
    #pragma unroll
    for (int i = 0; i < 4; ++i) { acc2[i][0] = 0ull; acc2[i][1] = 0ull; }

    // Global bases (k advances contiguously for both A operands)
    const float* A1 = x + ((size_t)(m0 + a_row) * T_ + (size_t)t) * D_ + a_k8;
    const float* B1 = Ww + (size_t)b_k * H_ + n0 + b_n4;
    const float* A2 = h_in + (size_t)(m0 + a_row) * H_ + a_k8;
    const float* B2 = Uw + (size_t)b_k * H_ + n0 + b_n4;

    float4 avA0, avA1, bvB0, bvB1, bvB2, bvB3;

#define LOAD_TILE(Aptr, Bptr, k0)                                   \
    do {                                                             \
        avA0 = *(const float4*)((Aptr) + (k0));                      \
        avA1 = *(const float4*)((Aptr) + (k0) + 4);                  \
        const float* _bp = (Bptr) + (size_t)(k0) * H_;               \
        bvB0 = *(const float4*)_bp;                                  \
        bvB1 = *(const float4*)(_bp + 8 * H_);                       \
        bvB2 = *(const float4*)(_bp + 16 * H_);                      \
        bvB3 = *(const float4*)(_bp + 24 * H_);                      \
    } while (0)

#define STORE_TILE(p)                                                \
    do {                                                             \
        As[p][a_k8 + 0][a_row] = avA0.x;                             \
        As[p][a_k8 + 1][a_row] = avA0.y;                             \
        As[p][a_k8 + 2][a_row] = avA0.z;                             \
        As[p][a_k8 + 3][a_row] = avA0.w;                             \
        As[p][a_k8 + 4][a_row] = avA1.x;                             \
        As[p][a_k8 + 5][a_row] = avA1.y;                             \
        As[p][a_k8 + 6][a_row] = avA1.z;                             \
        As[p][a_k8 + 7][a_row] = avA1.w;                             \
        *(float4*)&Bs[p][b_k][b_n4]      = bvB0;                     \
        *(float4*)&Bs[p][b_k +  8][b_n4] = bvB1;                     \
        *(float4*)&Bs[p][b_k + 16][b_n4] = bvB2;                     \
        *(float4*)&Bs[p][b_k + 24][b_n4] = bvB3;                     \
    } while (0)

#define COMPUTE_TILE(p)                                              \
    do {                                                             \
        _Pragma("unroll")                                            \
        for (int kk = 0; kk < TK; ++kk) {                            \
            float4 a = *(const float4*)&As[p][kk][mr];               \
            ulonglong2 b = *(const ulonglong2*)&Bs[p][kk][nc];       \
            unsigned long long a0 = dup2(a.x), a1 = dup2(a.y);       \
            unsigned long long a2 = dup2(a.z), a3 = dup2(a.w);       \
            fma2(acc2[0][0], a0, b.x); fma2(acc2[0][1], a0, b.y);    \
            fma2(acc2[1][0], a1, b.x); fma2(acc2[1][1], a1, b.y);    \
            fma2(acc2[2][0], a2, b.x); fma2(acc2[2][1], a2, b.y);    \
            fma2(acc2[3][0], a3, b.x); fma2(acc2[3][1], a3, b.y);    \
        }                                                            \
    } while (0)

    int p = 0;

    // Preload first tile of part 1
    LOAD_TILE(A1, B1, 0);
    STORE_TILE(0);
    __syncthreads();

    // ======== part 1: x_t @ Ww  (K = D_) ========
    #pragma unroll 1
    for (int k0 = TK; k0 < D_; k0 += TK) {
        LOAD_TILE(A1, B1, k0);
        COMPUTE_TILE(p);
        STORE_TILE(p ^ 1);
        __syncthreads();
        p ^= 1;
    }

    if (t > 0) {
        // bridge: prefetch first tile of part 2 while computing last of part 1
        LOAD_TILE(A2, B2, 0);
        COMPUTE_TILE(p);
        STORE_TILE(p ^ 1);
        __syncthreads();
        p ^= 1;

        // ======== part 2: h @ Uw  (K = H_) ========
        #pragma unroll 1
        for (int k0 = TK; k0 < H_; k0 += TK) {
            LOAD_TILE(A2, B2, k0);
            COMPUTE_TILE(p);
            STORE_TILE(p ^ 1);
            __syncthreads();
            p ^= 1;
        }
        COMPUTE_TILE(p);
    } else {
        COMPUTE_TILE(p);
    }

    // ======== epilogue: h_out = alpha*tanh(acc+bias) + beta*h_in ========
    #pragma unroll
    for (int i = 0; i < 4; ++i) {
        const int gm = m0 + mr + i;
        const size_t o = (size_t)gm * H_ + (size_t)(n0 + nc);
        float4 hp = make_float4(0.f, 0.f, 0.f, 0.f);
        if (t > 0) hp = *(const float4*)(h_in + o);
        float2 c01 = unpk2(acc2[i][0]);
        float2 c23 = unpk2(acc2[i][1]);
        float4 r;
        r.x = alpha * tanhf(c01.x + bias[0]) + beta * hp.x;
        r.y = alpha * tanhf(c01.y + bias[1]) + beta * hp.y;
        r.z = alpha * tanhf(c23.x + bias[2]) + beta * hp.z;
        r.w = alpha * tanhf(c23.y + bias[3]) + beta * hp.w;
        *(float4*)(h_out + o) = r;
    }

#undef LOAD_TILE
#undef STORE_TILE
#undef COMPUTE_TILE
}

// out[row, c] = h_final[row, :] @ fc_w[:, c] + fc_b[c]
// One CTA per batch row; warp w computes column w (C_=10 warps).
// Final h is in g_h[0] (T_ even), referenced on-device.
__global__ void fc_kernel(const float* __restrict__ fcw,
                          const float* __restrict__ fcb,
                          float* __restrict__ out)
{
    const float* __restrict__ h = &g_h[0][0];
    const int row  = blockIdx.x;
    const int warp = threadIdx.x >> 5;
    const int lane = threadIdx.x & 31;
    if (warp >= C_) return;
    float s = 0.f;
    const float* hr = h + (size_t)row * H_;
    for (int k = lane; k < H_; k += 32)
        s += hr[k] * fcw[k * C_ + warp];
    #pragma unroll
    for (int off = 16; off > 0; off >>= 1)
        s += __shfl_down_sync(0xffffffffu, s, off);
    if (lane == 0) out[row * C_ + warp] = s + fcb[warp];
}

extern "C" void kernel_launch(void* const* d_in, const int* in_sizes, int n_in,
                              void* d_out, int out_size)
{
    (void)in_sizes; (void)n_in; (void)out_size;
    const float* x   = (const float*)d_in[0];
    const float* Ww  = (const float*)d_in[1];
    const float* Wb  = (const float*)d_in[2];
    const float* Uw  = (const float*)d_in[3];
    const float* Ub  = (const float*)d_in[4];
    const float* al  = (const float*)d_in[5];
    const float* be  = (const float*)d_in[6];
    const float* fcw = (const float*)d_in[7];
    const float* fcb = (const float*)d_in[8];

    for (int t = 0; t < T_; ++t)
        step_kernel<<<NCTA, NTHR>>>(x, Ww, Wb, Uw, Ub, al, be, t);

    fc_kernel<<<B_, 32 * C_>>>(fcw, fcb, (float*)d_out);
}

// round 8
// speedup vs baseline: 1.7782x; 1.7782x over previous
#include <cuda_runtime.h>
#include <cuda_bf16.h>
#include <cstdint>
#include <cstddef>

#define B_ 256
#define T_ 256
#define D_ 512
#define H_ 1024
#define C_ 10

// ---------------- device scratch (allocation-free: __device__ globals) ------
__device__ float g_wx[(size_t)B_ * T_ * H_];           // x@Ww + Wb + Ub
__device__ float g_h[2][B_ * H_];                      // fp32 h ping-pong
__device__ __nv_bfloat16 g_hs[2][2][B_ * H_];          // bf16 hi/lo of h
__device__ __nv_bfloat16 g_Ut[2][(size_t)H_ * H_];     // U^T splits [n][k]
__device__ __nv_bfloat16 g_Wt[2][(size_t)H_ * D_];     // Ww^T splits [n][k]
__device__ __nv_bfloat16 g_xs[2][(size_t)B_ * T_ * D_];// x splits [m][d]

// ---------------- helpers ---------------------------------------------------
__device__ __forceinline__ uint32_t smem_u32(const void* p) {
    uint32_t a;
    asm("{ .reg .u64 t; cvta.to.shared.u64 t, %1; cvt.u32.u64 %0, t; }" : "=r"(a) : "l"(p));
    return a;
}
__device__ __forceinline__ void cpa16(uint32_t dst, const void* src) {
    asm volatile("cp.async.cg.shared.global [%0], [%1], 16;" :: "r"(dst), "l"(src) : "memory");
}
#define CP_COMMIT() asm volatile("cp.async.commit_group;" ::: "memory")

__device__ __forceinline__ void ldsm4(uint32_t& r0, uint32_t& r1, uint32_t& r2, uint32_t& r3,
                                      uint32_t addr) {
    asm volatile("ldmatrix.sync.aligned.m8n8.x4.shared.b16 {%0,%1,%2,%3}, [%4];"
                 : "=r"(r0), "=r"(r1), "=r"(r2), "=r"(r3) : "r"(addr));
}
__device__ __forceinline__ void mma16816(float* c, uint32_t a0, uint32_t a1, uint32_t a2,
                                         uint32_t a3, uint32_t b0, uint32_t b1) {
    asm volatile(
        "mma.sync.aligned.m16n8k16.row.col.f32.bf16.bf16.f32 "
        "{%0,%1,%2,%3}, {%4,%5,%6,%7}, {%8,%9}, {%0,%1,%2,%3};"
        : "+f"(c[0]), "+f"(c[1]), "+f"(c[2]), "+f"(c[3])
        : "r"(a0), "r"(a1), "r"(a2), "r"(a3), "r"(b0), "r"(b1));
}
__device__ __forceinline__ void split2(float v, __nv_bfloat16& hi, __nv_bfloat16& lo) {
    hi = __float2bfloat16(v);
    lo = __float2bfloat16(v - __bfloat162float(hi));
}

// ---------------- step kernel geometry --------------------------------------
// tile 32(M) x 64(N), KC=64, 8 warps, warp tile 16x16
#define KC_S   64
#define NCH_S  (H_ / KC_S)     // 16
#define ROWB_S 144             // (64+8) bf16 per row
#define S_AHI  0
#define S_ALO  4608
#define S_BHI  9216
#define S_BLO  18432
#define S_STAGE 27648
#define S_SMEM (2 * S_STAGE)   // 55296

// ---------------- wx kernel geometry ----------------------------------------
// tile 128(M) x 64(N), KC=32, 8 warps, warp tile 32x32
#define KC_W   32
#define NCH_W  (D_ / KC_W)     // 16
#define ROWB_W 80              // (32+8) bf16 per row
#define W_AHI  0
#define W_ALO  10240
#define W_BHI  20480
#define W_BLO  25600
#define W_STAGE 30720
#define W_SMEM (2 * W_STAGE)   // 61440

// ======================= converter: splits of U^T, Ww^T, x ==================
__global__ void conv_kernel(const float* __restrict__ Uw,
                            const float* __restrict__ Ww,
                            const float* __restrict__ x)
{
    const size_t nu = (size_t)H_ * H_;
    const size_t nw = (size_t)D_ * H_;
    const size_t nx = (size_t)B_ * T_ * D_;
    const size_t total = nu + nw + nx;
    for (size_t i = (size_t)blockIdx.x * blockDim.x + threadIdx.x; i < total;
         i += (size_t)gridDim.x * blockDim.x) {
        __nv_bfloat16 hi, lo;
        if (i < nu) {
            size_t k = i >> 10, n = i & (H_ - 1);
            split2(Uw[k * H_ + n], hi, lo);
            g_Ut[0][n * H_ + k] = hi;
            g_Ut[1][n * H_ + k] = lo;
        } else if (i < nu + nw) {
            size_t j = i - nu;
            size_t k = j >> 10, n = j & (H_ - 1);
            split2(Ww[k * H_ + n], hi, lo);
            g_Wt[0][n * D_ + k] = hi;
            g_Wt[1][n * D_ + k] = lo;
        } else {
            size_t j = i - nu - nw;
            split2(x[j], hi, lo);
            g_xs[0][j] = hi;
            g_xs[1][j] = lo;
        }
    }
}

// ======================= wx = x @ Ww + (Wb+Ub) ==============================
// Grid: 512 M-tiles(128) x 16 N-tiles(64) = 8192 CTAs, 256 threads.
__global__ void __launch_bounds__(256, 1) wx_kernel(
    const float* __restrict__ Wb, const float* __restrict__ Ub)
{
    extern __shared__ char smem[];
    const uint32_t sb = smem_u32(smem);
    const int tid = threadIdx.x;
    const int w = tid >> 5, lane = tid & 31;
    const int m0 = (blockIdx.x >> 4) * 128;
    const int n0 = (blockIdx.x & 15) * 64;
    const int m_off = (w & 3) * 32;
    const int n_off = (w >> 2) * 32;

    float acc[2][4][4];
    #pragma unroll
    for (int a = 0; a < 2; ++a)
        #pragma unroll
        for (int b = 0; b < 4; ++b)
            #pragma unroll
            for (int cc = 0; cc < 4; ++cc) acc[a][b][cc] = 0.f;

    // loader: A 4 units/thread/stage, B 2 units/thread/stage
#define W_LOAD(buf, k0)                                                        \
    do {                                                                       \
        const uint32_t st = sb + (buf) * W_STAGE;                              \
        _Pragma("unroll")                                                      \
        for (int i = 0; i < 4; ++i) {                                          \
            int u = tid * 4 + i;                                               \
            int s = u >> 9, v = u & 511;                                       \
            int row = v >> 2, kg = v & 3;                                      \
            cpa16(st + s * 10240 + row * ROWB_W + kg * 16,                     \
                  &g_xs[s][(size_t)(m0 + row) * D_ + (k0) + kg * 8]);          \
        }                                                                      \
        _Pragma("unroll")                                                      \
        for (int i = 0; i < 2; ++i) {                                          \
            int u = tid * 2 + i;                                               \
            int s = u >> 8, v = u & 255;                                       \
            int row = v >> 2, kg = v & 3;                                      \
            cpa16(st + W_BHI + s * 5120 + row * ROWB_W + kg * 16,              \
                  &g_Wt[s][(size_t)(n0 + row) * D_ + (k0) + kg * 8]);          \
        }                                                                      \
        CP_COMMIT();                                                           \
    } while (0)

    W_LOAD(0, 0);
    W_LOAD(1, KC_W);

    #pragma unroll 1
    for (int c = 0; c < NCH_W; ++c) {
        if (c + 1 < NCH_W) asm volatile("cp.async.wait_group 1;" ::: "memory");
        else               asm volatile("cp.async.wait_group 0;" ::: "memory");
        __syncthreads();
        const uint32_t bb = sb + (c & 1) * W_STAGE;

        #pragma unroll
        for (int kk = 0; kk < KC_W; kk += 16) {
            const uint32_t aoff =
                (uint32_t)((m_off + (lane & 15)) * ROWB_W + (kk + (lane >> 4) * 8) * 2);
            const uint32_t aoff2 = aoff + 16 * ROWB_W;
            const uint32_t boff =
                (uint32_t)((n_off + ((lane >> 4) * 8) + (lane & 7)) * ROWB_W +
                           (kk + ((lane >> 3) & 1) * 8) * 2);
            const uint32_t boff2 = boff + 16 * ROWB_W;

            uint32_t ah[2][4], al[2][4], bh[2][4], bl[2][4];
            ldsm4(ah[0][0], ah[0][1], ah[0][2], ah[0][3], bb + W_AHI + aoff);
            ldsm4(ah[1][0], ah[1][1], ah[1][2], ah[1][3], bb + W_AHI + aoff2);
            ldsm4(al[0][0], al[0][1], al[0][2], al[0][3], bb + W_ALO + aoff);
            ldsm4(al[1][0], al[1][1], al[1][2], al[1][3], bb + W_ALO + aoff2);
            ldsm4(bh[0][0], bh[0][1], bh[0][2], bh[0][3], bb + W_BHI + boff);
            ldsm4(bh[1][0], bh[1][1], bh[1][2], bh[1][3], bb + W_BHI + boff2);
            ldsm4(bl[0][0], bl[0][1], bl[0][2], bl[0][3], bb + W_BLO + boff);
            ldsm4(bl[1][0], bl[1][1], bl[1][2], bl[1][3], bb + W_BLO + boff2);

            #pragma unroll
            for (int mi = 0; mi < 2; ++mi)
                #pragma unroll
                for (int ni = 0; ni < 4; ++ni) {
                    uint32_t p0 = (ni & 2) ? bh[1][(ni & 1) * 2]     : bh[0][(ni & 1) * 2];
                    uint32_t p1 = (ni & 2) ? bh[1][(ni & 1) * 2 + 1] : bh[0][(ni & 1) * 2 + 1];
                    uint32_t q0 = (ni & 2) ? bl[1][(ni & 1) * 2]     : bl[0][(ni & 1) * 2];
                    uint32_t q1 = (ni & 2) ? bl[1][(ni & 1) * 2 + 1] : bl[0][(ni & 1) * 2 + 1];
                    mma16816(acc[mi][ni], ah[mi][0], ah[mi][1], ah[mi][2], ah[mi][3], p0, p1);
                    mma16816(acc[mi][ni], ah[mi][0], ah[mi][1], ah[mi][2], ah[mi][3], q0, q1);
                    mma16816(acc[mi][ni], al[mi][0], al[mi][1], al[mi][2], al[mi][3], p0, p1);
                }
        }
        __syncthreads();
        if (c + 2 < NCH_W) W_LOAD(c & 1, (c + 2) * KC_W);
    }
#undef W_LOAD

    // epilogue: add biases, store fp32 wx
    const int g = lane >> 2, qc = (lane & 3) * 2;
    #pragma unroll
    for (int mi = 0; mi < 2; ++mi)
        #pragma unroll
        for (int ni = 0; ni < 4; ++ni) {
            const int col = n0 + n_off + ni * 8 + qc;
            const float bsum0 = Wb[col] + Ub[col];
            const float bsum1 = Wb[col + 1] + Ub[col + 1];
            #pragma unroll
            for (int hf = 0; hf < 2; ++hf) {
                const int row = m0 + m_off + mi * 16 + g + hf * 8;
                float2 r = make_float2(acc[mi][ni][hf * 2] + bsum0,
                                       acc[mi][ni][hf * 2 + 1] + bsum1);
                *(float2*)&g_wx[(size_t)row * H_ + col] = r;
            }
        }
}

// ======================= t = 0: h1 = alpha * tanh(wx_0) =====================
__global__ void t0_kernel(const float* __restrict__ alpha_p)
{
    const float alpha = alpha_p[0];
    const int b = blockIdx.x;
    for (int n = threadIdx.x; n < H_; n += blockDim.x) {
        float pre = g_wx[((size_t)b * T_ + 0) * H_ + n];
        float hv = alpha * tanhf(pre);
        g_h[1][b * H_ + n] = hv;
        __nv_bfloat16 hi, lo;
        split2(hv, hi, lo);
        g_hs[1][0][b * H_ + n] = hi;
        g_hs[1][1][b * H_ + n] = lo;
    }
}

// ======================= recurrence step (t = 1..255) =======================
// h_{t+1} = alpha*tanh(h_t @ U + wx_t) + beta*h_t
// Grid: 8 M-tiles(32) x 16 N-tiles(64) = 128 CTAs, 256 threads.
__global__ void __launch_bounds__(256, 1) step_kernel(
    const float* __restrict__ alpha_p, const float* __restrict__ beta_p, int t)
{
    extern __shared__ char smem[];
    const uint32_t sb = smem_u32(smem);
    const int tid = threadIdx.x;
    const int w = tid >> 5, lane = tid & 31;
    const int m0 = (blockIdx.x & 7) * 32;
    const int n0 = (blockIdx.x >> 3) * 64;
    const int m_half = (w & 1) * 16;
    const int n_off  = (w >> 1) * 16;

    const __nv_bfloat16* __restrict__ hs0 = &g_hs[t & 1][0][0];
    const __nv_bfloat16* __restrict__ hs1 = &g_hs[t & 1][1][0];

    float acc[2][4];
    #pragma unroll
    for (int a = 0; a < 2; ++a)
        #pragma unroll
        for (int cc = 0; cc < 4; ++cc) acc[a][cc] = 0.f;

#define S_LOAD(buf, k0)                                                        \
    do {                                                                       \
        const uint32_t st = sb + (buf) * S_STAGE;                              \
        _Pragma("unroll")                                                      \
        for (int i = 0; i < 2; ++i) {                                          \
            int u = tid * 2 + i;                                               \
            int s = u >> 8, v = u & 255;                                       \
            int row = v >> 3, kg = v & 7;                                      \
            const __nv_bfloat16* src =                                         \
                (s ? hs1 : hs0) + (size_t)(m0 + row) * H_ + (k0) + kg * 8;     \
            cpa16(st + s * 4608 + row * ROWB_S + kg * 16, src);                \
        }                                                                      \
        _Pragma("unroll")                                                      \
        for (int i = 0; i < 4; ++i) {                                          \
            int u = tid * 4 + i;                                               \
            int s = u >> 9, v = u & 511;                                       \
            int row = v >> 3, kg = v & 7;                                      \
            cpa16(st + S_BHI + s * 9216 + row * ROWB_S + kg * 16,              \
                  &g_Ut[s][(size_t)(n0 + row) * H_ + (k0) + kg * 8]);          \
        }                                                                      \
        CP_COMMIT();                                                           \
    } while (0)

    S_LOAD(0, 0);
    S_LOAD(1, KC_S);

    #pragma unroll 1
    for (int c = 0; c < NCH_S; ++c) {
        if (c + 1 < NCH_S) asm volatile("cp.async.wait_group 1;" ::: "memory");
        else               asm volatile("cp.async.wait_group 0;" ::: "memory");
        __syncthreads();
        const uint32_t bb = sb + (c & 1) * S_STAGE;

        #pragma unroll
        for (int kk = 0; kk < KC_S; kk += 16) {
            const uint32_t aoff =
                (uint32_t)((m_half + (lane & 15)) * ROWB_S + (kk + (lane >> 4) * 8) * 2);
            const uint32_t boff =
                (uint32_t)((n_off + ((lane >> 4) * 8) + (lane & 7)) * ROWB_S +
                           (kk + ((lane >> 3) & 1) * 8) * 2);

            uint32_t ah[4], al[4], bh[4], bl[4];
            ldsm4(ah[0], ah[1], ah[2], ah[3], bb + S_AHI + aoff);
            ldsm4(al[0], al[1], al[2], al[3], bb + S_ALO + aoff);
            ldsm4(bh[0], bh[1], bh[2], bh[3], bb + S_BHI + boff);
            ldsm4(bl[0], bl[1], bl[2], bl[3], bb + S_BLO + boff);

            mma16816(acc[0], ah[0], ah[1], ah[2], ah[3], bh[0], bh[1]);
            mma16816(acc[1], ah[0], ah[1], ah[2], ah[3], bh[2], bh[3]);
            mma16816(acc[0], ah[0], ah[1], ah[2], ah[3], bl[0], bl[1]);
            mma16816(acc[1], ah[0], ah[1], ah[2], ah[3], bl[2], bl[3]);
            mma16816(acc[0], al[0], al[1], al[2], al[3], bh[0], bh[1]);
            mma16816(acc[1], al[0], al[1], al[2], al[3], bh[2], bh[3]);
        }
        __syncthreads();
        if (c + 2 < NCH_S) S_LOAD(c & 1, (c + 2) * KC_S);
    }
#undef S_LOAD

    // ---- epilogue ----
    const float alpha = alpha_p[0];
    const float beta  = beta_p[0];
    const float* __restrict__ hin = &g_h[t & 1][0];
    float* __restrict__ hout      = &g_h[(t + 1) & 1][0];
    __nv_bfloat16* __restrict__ hop = &g_hs[(t + 1) & 1][0][0];
    __nv_bfloat16* __restrict__ lop = &g_hs[(t + 1) & 1][1][0];
    const int g = lane >> 2, qc = (lane & 3) * 2;

    #pragma unroll
    for (int nb = 0; nb < 2; ++nb) {
        const int col = n0 + n_off + nb * 8 + qc;
        #pragma unroll
        for (int hf = 0; hf < 2; ++hf) {
            const int row = m0 + m_half + g + hf * 8;
            const size_t o = (size_t)row * H_ + col;
            const float* wxp = &g_wx[((size_t)row * T_ + t) * H_ + col];
            float pre0 = acc[nb][hf * 2]     + wxp[0];
            float pre1 = acc[nb][hf * 2 + 1] + wxp[1];
            float2 hi2 = *(const float2*)&hin[o];
            float h0 = alpha * tanhf(pre0) + beta * hi2.x;
            float h1 = alpha * tanhf(pre1) + beta * hi2.y;
            *(float2*)&hout[o] = make_float2(h0, h1);
            __nv_bfloat16 a0, b0, a1, b1;
            split2(h0, a0, b0);
            split2(h1, a1, b1);
            __nv_bfloat162 hh = {a0, a1}, ll = {b0, b1};
            *(uint32_t*)&hop[o] = *(uint32_t*)&hh;
            *(uint32_t*)&lop[o] = *(uint32_t*)&ll;
        }
    }
}

// ======================= final FC ==========================================
__global__ void fc_kernel(const float* __restrict__ fcw,
                          const float* __restrict__ fcb,
                          float* __restrict__ out)
{
    const float* __restrict__ h = &g_h[0][0];   // h_256 (T_ even)
    const int row  = blockIdx.x;
    const int warp = threadIdx.x >> 5;
    const int lane = threadIdx.x & 31;
    if (warp >= C_) return;
    float s = 0.f;
    const float* hr = h + (size_t)row * H_;
    for (int k = lane; k < H_; k += 32)
        s += hr[k] * fcw[k * C_ + warp];
    #pragma unroll
    for (int off = 16; off > 0; off >>= 1)
        s += __shfl_down_sync(0xffffffffu, s, off);
    if (lane == 0) out[row * C_ + warp] = s + fcb[warp];
}

// ======================= host ==============================================
extern "C" void kernel_launch(void* const* d_in, const int* in_sizes, int n_in,
                              void* d_out, int out_size)
{
    (void)in_sizes; (void)n_in; (void)out_size;
    const float* x   = (const float*)d_in[0];
    const float* Ww  = (const float*)d_in[1];
    const float* Wb  = (const float*)d_in[2];
    const float* Uw  = (const float*)d_in[3];
    const float* Ub  = (const float*)d_in[4];
    const float* al  = (const float*)d_in[5];
    const float* be  = (const float*)d_in[6];
    const float* fcw = (const float*)d_in[7];
    const float* fcb = (const float*)d_in[8];

    cudaFuncSetAttribute(wx_kernel,   cudaFuncAttributeMaxDynamicSharedMemorySize, W_SMEM);
    cudaFuncSetAttribute(step_kernel, cudaFuncAttributeMaxDynamicSharedMemorySize, S_SMEM);

    conv_kernel<<<8192, 256>>>(Uw, Ww, x);
    wx_kernel<<<8192, 256, W_SMEM>>>(Wb, Ub);
    t0_kernel<<<B_, 256>>>(al);
    for (int t = 1; t < T_; ++t)
        step_kernel<<<128, 256, S_SMEM>>>(al, be, t);
    fc_kernel<<<B_, 32 * C_>>>(fcw, fcb, (float*)d_out);
}